// round 16
// baseline (speedup 1.0000x reference)
#include <cuda_runtime.h>
#include <cuda_fp16.h>
#include <cstdint>

// FwFM second-order via mma.sync fp16, warp-private cp.async pipelines.
//   out[c] = sum_l x[l,c] * T[l,c],  T: A = X^T (M=cols), B = L^T (N=l).
// Each warp owns a 16-col tile stream + private double buffer; no block
// barriers in the main loop (cp.async groups are per-warp state).
// kt=2 high-half A fragments (k=40..47) are zero in registers (B zero there),
// so smem only holds rows 0..39 (row 39 zeroed).

#define KF 39
#define BD (8192 * 64)
#define THREADS 256          // 8 warps
#define NWARP 8
#define TILES 4              // tiles per warp (compile-time -> unrolled)
#define WCOLS 16             // columns per warp-tile
#define PITCH 20             // floats per k-row (80B): conflict-free, 16B-aligned
#define KROWS 40             // 39 data rows + 1 zeroed (k=39 feeds kt=2 a0/a1)
#define WBUF (KROWS * PITCH) // 800 floats per stage (3200B, 16B-aligned)
#define WREG (2 * WBUF)      // per-warp smem floats (2 stages)
#define NTILE 9

typedef unsigned int u32;

__constant__ int c_kt[NTILE] = {0, 0, 0, 0, 0, 1, 1, 1, 2};
__constant__ int c_nt[NTILE] = {0, 1, 2, 3, 4, 2, 3, 4, 4};

static __device__ __forceinline__ void mma_f16(float* d, const u32* a, u32 b0, u32 b1) {
    asm volatile(
        "mma.sync.aligned.m16n8k16.row.col.f32.f16.f16.f32 "
        "{%0,%1,%2,%3}, {%4,%5,%6,%7}, {%8,%9}, {%0,%1,%2,%3};"
        : "+f"(d[0]), "+f"(d[1]), "+f"(d[2]), "+f"(d[3])
        : "r"(a[0]), "r"(a[1]), "r"(a[2]), "r"(a[3]), "r"(b0), "r"(b1));
}
static __device__ __forceinline__ u32 smem_u32(const void* p) {
    u32 a;
    asm("{ .reg .u64 t; cvta.to.shared.u64 t, %1; cvt.u32.u64 %0, t; }" : "=r"(a) : "l"(p));
    return a;
}
static __device__ __forceinline__ void cp16(u32 s, const void* g) {
    asm volatile("cp.async.cg.shared.global [%0], [%1], 16;" :: "r"(s), "l"(g) : "memory");
}
static __device__ __forceinline__ u32 packh2(float a, float b) {
    __half2 h = __floats2half2_rn(a, b);
    return *(u32*)&h;
}

__global__ __launch_bounds__(THREADS, 4)
void fwfm_main(const float* __restrict__ x,
               const float* __restrict__ W,
               float* __restrict__ out) {
    extern __shared__ float Xs[];   // [NWARP][2][KROWS][PITCH]

    const int tid = threadIdx.x;
    const int wid = tid >> 5, lane = tid & 31;
    const int g = lane >> 2, tq = lane & 3;
    float* wb = Xs + wid * WREG;                       // this warp's buffers
    const size_t cta_col = (size_t)blockIdx.x * (NWARP * TILES * WCOLS);
    const int ldrow8 = lane >> 2;                      // 0..7
    const int ldoff = (lane & 3) * 4;                  // 16B chunk in 64B row

    // ---- issue tile-0 load immediately (warp-private) ----
    {
        const float* src = x + cta_col + (size_t)(wid * WCOLS) + ldoff;
        u32 dst = smem_u32(wb) + (u32)(ldoff * 4);
#pragma unroll
        for (int it = 0; it < 5; ++it) {
            int row = it * 8 + ldrow8;
            if (row < KF)
                cp16(dst + (u32)(row * PITCH * 4), src + (size_t)row * BD);
        }
        asm volatile("cp.async.commit_group;" ::: "memory");
    }

    // ---- zero pad row 39 of both stages (warp-private) ----
    for (int i = lane; i < 2 * (KROWS - KF) * PITCH; i += 32) {
        int stg = i / ((KROWS - KF) * PITCH);
        int r = i - stg * ((KROWS - KF) * PITCH);
        wb[stg * WBUF + KF * PITCH + r] = 0.0f;
    }

    // ---- build B fragments from W (cached scattered loads, hide under tile-0) ----
    u32 bf[NTILE][2];
#pragma unroll
    for (int t = 0; t < NTILE; ++t) {
        const int l = c_nt[t] * 8 + g;
        const int k0 = c_kt[t] * 16 + 2 * tq;
        float v[4];
#pragma unroll
        for (int dd = 0; dd < 4; ++dd) {
            int k = k0 + (dd >> 1) * 8 + (dd & 1);
            v[dd] = (l < KF && k < l) ? 0.5f * (__ldg(W + k * KF + l) + __ldg(W + l * KF + k))
                                      : 0.0f;
        }
        bf[t][0] = packh2(v[0], v[1]);
        bf[t][1] = packh2(v[2], v[3]);
    }
    __syncwarp();

#pragma unroll
    for (int t = 0; t < TILES; ++t) {
        if (t + 1 < TILES) {
            const float* src = x + cta_col + (size_t)(((t + 1) * NWARP + wid) * WCOLS) + ldoff;
            u32 dst = smem_u32(wb + ((t + 1) & 1) * WBUF) + (u32)(ldoff * 4);
#pragma unroll
            for (int it = 0; it < 5; ++it) {
                int row = it * 8 + ldrow8;
                if (row < KF)
                    cp16(dst + (u32)(row * PITCH * 4), src + (size_t)row * BD);
            }
            asm volatile("cp.async.commit_group;" ::: "memory");
            asm volatile("cp.async.wait_group 1;" ::: "memory");
        } else {
            asm volatile("cp.async.wait_group 0;" ::: "memory");
        }
        __syncwarp();   // tile (t) data visible warp-wide

        const float* B = wb + (t & 1) * WBUF;

        float d[5][4];
#pragma unroll
        for (int nt = 0; nt < 5; ++nt)
#pragma unroll
            for (int r = 0; r < 4; ++r) d[nt][r] = 0.0f;

#pragma unroll
        for (int kt = 0; kt < 3; ++kt) {
            // A fragment: rows kt*16+2tq(+1,+8,+9), cols g(+8) of this 16-col tile.
            // kt=2: rows +8/+9 are k=40..47 where B==0 -> zero registers, no load.
            const float* ap = B + (kt * 16 + 2 * tq) * PITCH + g;
            u32 a[4];
            a[0] = packh2(ap[0], ap[PITCH]);
            a[1] = packh2(ap[8], ap[PITCH + 8]);
            if (kt < 2) {
                a[2] = packh2(ap[8 * PITCH], ap[9 * PITCH]);
                a[3] = packh2(ap[8 * PITCH + 8], ap[9 * PITCH + 8]);
            } else {
                a[2] = 0u;
                a[3] = 0u;
            }
            if (kt == 0) {
#pragma unroll
                for (int q = 0; q < 5; ++q) mma_f16(d[q], a, bf[q][0], bf[q][1]);
            } else if (kt == 1) {
#pragma unroll
                for (int q = 5; q < 8; ++q) mma_f16(d[q - 3], a, bf[q][0], bf[q][1]);
            } else {
                mma_f16(d[4], a, bf[8][0], bf[8][1]);
            }
        }

        // Epilogue: out[c] = sum_l x[l,c]*T[l,c]; conflict-free fp32 LDS (rows <= 39).
        {
            const float* xg = B + g;
            float sg = 0.0f, sg8 = 0.0f;
#pragma unroll
            for (int nt = 0; nt < 5; ++nt) {
                const int l0 = nt * 8 + 2 * tq;
                sg = fmaf(xg[l0 * PITCH], d[nt][0], sg);
                sg = fmaf(xg[(l0 + 1) * PITCH], d[nt][1], sg);
                sg8 = fmaf(xg[l0 * PITCH + 8], d[nt][2], sg8);
                sg8 = fmaf(xg[(l0 + 1) * PITCH + 8], d[nt][3], sg8);
            }
            sg += __shfl_xor_sync(0xFFFFFFFFu, sg, 1);
            sg += __shfl_xor_sync(0xFFFFFFFFu, sg, 2);
            sg8 += __shfl_xor_sync(0xFFFFFFFFu, sg8, 1);
            sg8 += __shfl_xor_sync(0xFFFFFFFFu, sg8, 2);
            if (tq == 0) {
                float* o = out + cta_col + (size_t)((t * NWARP + wid) * WCOLS) + g;
                o[0] = sg;
                o[8] = sg8;
            }
        }
        __syncwarp();   // stage reads done before next overwrite of this stage
    }
}

extern "C" void kernel_launch(void* const* d_in, const int* in_sizes, int n_in,
                              void* d_out, int out_size) {
    const float* x = (const float*)d_in[0];   // [39, 8192, 64] fp32
    const float* W = (const float*)d_in[1];   // [39, 39] fp32
    float* out = (float*)d_out;               // [8192, 64] fp32

    const int smem = NWARP * WREG * (int)sizeof(float);   // 51200 B -> 4 CTAs/SM
    cudaFuncSetAttribute(fwfm_main, cudaFuncAttributeMaxDynamicSharedMemorySize, smem);

    fwfm_main<<<BD / (NWARP * TILES * WCOLS), THREADS, smem>>>(x, W, out);
}